// round 6
// baseline (speedup 1.0000x reference)
#include <cuda_runtime.h>

#define MAX_N 100000
#define MAX_E 1600000

// ---------------- scratch (static __device__ arrays) ----------------------
__device__ float g_h1   [MAX_N * 64];
__device__ float g_als1 [MAX_N * 4];
__device__ float g_ald1 [MAX_N * 4];
__device__ float g_out1 [MAX_N * 64];
__device__ float g_h2   [MAX_N * 128];
__device__ float g_als2 [MAX_N * 4];
__device__ float g_ald2 [MAX_N * 4];
__device__ int   g_rowptr[MAX_N + 1];
__device__ int   g_cursor[MAX_N];
__device__ int   g_bsum[128];
__device__ int   g_ssrc[MAX_E];
__device__ float g_fold1[128 * 8];   // [k][q]: q<4 -> W1@a_src1, q>=4 -> W1@a_dst1
__device__ float g_fold2[64 * 8];    // [k][q]: from W2/a2

// ---------------- GEMM: C[M,NC] = A[M,K] @ W[K,NC] ------------------------
template<int K, int NC>
__global__ __launch_bounds__(16 * (NC / 8))
void gemm_kernel(const float* __restrict__ A, const float* __restrict__ W,
                 float* __restrict__ C, int M)
{
    constexpr int KC = 32;
    constexpr int TX = NC / 8;
    constexpr int T  = 16 * TX;
    constexpr int A_F4 = (128 * KC / 4) / T;
    constexpr int B_F4 = (KC * NC / 4) / T;

    __shared__ float As[128][33];
    __shared__ float Bs[KC][NC];

    const int tid = threadIdx.x;
    const int tx = tid % TX;
    const int ty = tid / TX;
    const int row0 = blockIdx.x * 128;

    float4 aPre[A_F4], bPre[B_F4];

    auto loadA = [&](int kk) {
#pragma unroll
        for (int t = 0; t < A_F4; t++) {
            int q = tid + t * T;
            int r = q >> 3, kc4 = q & 7;
            int gr = row0 + r;
            aPre[t] = (gr < M)
                ? *(const float4*)(A + (size_t)gr * K + kk + kc4 * 4)
                : make_float4(0.f, 0.f, 0.f, 0.f);
        }
    };
    auto loadB = [&](int kk) {
#pragma unroll
        for (int t = 0; t < B_F4; t++) {
            int q = tid + t * T;
            int r = q / (NC / 4), c4 = q % (NC / 4);
            bPre[t] = *(const float4*)(W + (size_t)(kk + r) * NC + c4 * 4);
        }
    };
    auto storeA = [&]() {
#pragma unroll
        for (int t = 0; t < A_F4; t++) {
            int q = tid + t * T;
            int r = q >> 3, kc4 = q & 7;
            As[r][kc4 * 4 + 0] = aPre[t].x;
            As[r][kc4 * 4 + 1] = aPre[t].y;
            As[r][kc4 * 4 + 2] = aPre[t].z;
            As[r][kc4 * 4 + 3] = aPre[t].w;
        }
    };
    auto storeB = [&]() {
#pragma unroll
        for (int t = 0; t < B_F4; t++) {
            int q = tid + t * T;
            int r = q / (NC / 4), c4 = q % (NC / 4);
            *(float4*)&Bs[r][c4 * 4] = bPre[t];
        }
    };

    float acc[8][8];
#pragma unroll
    for (int i = 0; i < 8; i++)
#pragma unroll
        for (int j = 0; j < 8; j++) acc[i][j] = 0.f;

    loadA(0); loadB(0);
    storeA(); storeB();
    __syncthreads();

    for (int kk = KC; kk <= K; kk += KC) {
        const bool more = (kk < K);
        if (more) { loadA(kk); loadB(kk); }

#pragma unroll
        for (int k = 0; k < KC; k++) {
            float a[8];
#pragma unroll
            for (int i = 0; i < 8; i++) a[i] = As[ty * 8 + i][k];
            float4 b0 = *(float4*)&Bs[k][tx * 8];
            float4 b1 = *(float4*)&Bs[k][tx * 8 + 4];
#pragma unroll
            for (int i = 0; i < 8; i++) {
                acc[i][0] = fmaf(a[i], b0.x, acc[i][0]);
                acc[i][1] = fmaf(a[i], b0.y, acc[i][1]);
                acc[i][2] = fmaf(a[i], b0.z, acc[i][2]);
                acc[i][3] = fmaf(a[i], b0.w, acc[i][3]);
                acc[i][4] = fmaf(a[i], b1.x, acc[i][4]);
                acc[i][5] = fmaf(a[i], b1.y, acc[i][5]);
                acc[i][6] = fmaf(a[i], b1.z, acc[i][6]);
                acc[i][7] = fmaf(a[i], b1.w, acc[i][7]);
            }
        }
        __syncthreads();
        if (more) {
            storeA(); storeB();
            __syncthreads();
        }
    }

#pragma unroll
    for (int i = 0; i < 8; i++) {
        int gr = row0 + ty * 8 + i;
        if (gr < M) {
            *(float4*)(C + (size_t)gr * NC + tx * 8) =
                make_float4(acc[i][0], acc[i][1], acc[i][2], acc[i][3]);
            *(float4*)(C + (size_t)gr * NC + tx * 8 + 4) =
                make_float4(acc[i][4], acc[i][5], acc[i][6], acc[i][7]);
        }
    }
}

// ---------------- weight folds --------------------------------------------
// fold1[k][q] = sum_{c<16} W1[k, h*16+c] * a1q[h][c]   (k<128, q<8, h=q&3)
__global__ void build_fold1(const float* __restrict__ W1,
                            const float* __restrict__ as1,
                            const float* __restrict__ ad1,
                            float* __restrict__ fold)
{
    int t = threadIdx.x;            // 1024 threads
    int k = t >> 3, q = t & 7, h = q & 3;
    const float* a = (q < 4) ? as1 : ad1;
    float s = 0.f;
#pragma unroll
    for (int c = 0; c < 16; c++)
        s += W1[(size_t)k * 64 + h * 16 + c] * a[h * 16 + c];
    fold[k * 8 + q] = s;
}

// fold2[k][q] = sum_{c<32} W2[k, h*32+c] * a2q[h][c]   (k<64, q<8)
__global__ void build_fold2(const float* __restrict__ W2,
                            const float* __restrict__ as2,
                            const float* __restrict__ ad2,
                            float* __restrict__ fold)
{
    int t = threadIdx.x;            // 512 threads
    int k = t >> 3, q = t & 7, h = q & 3;
    const float* a = (q < 4) ? as2 : ad2;
    float s = 0.f;
#pragma unroll
    for (int c = 0; c < 32; c++)
        s += W2[(size_t)k * 128 + h * 32 + c] * a[h * 32 + c];
    fold[k * 8 + q] = s;
}

// ---------------- logits from features: warp per node ---------------------
// D = feature dim (64 or 128). als/ald[node][head] = feat[node] . fold[:,q]
template<int D>
__global__ void al_fold_kernel(const float* __restrict__ feat,
                               const float* __restrict__ fold,
                               float* __restrict__ als, float* __restrict__ ald,
                               int n)
{
    constexpr int PL = D / 32;      // floats per lane (2 or 4)
    __shared__ float sf[D * 8];
    for (int i = threadIdx.x; i < D * 8; i += blockDim.x) sf[i] = fold[i];
    __syncthreads();

    int lane = threadIdx.x & 31;
    int node = (blockIdx.x * blockDim.x + threadIdx.x) >> 5;
    if (node >= n) return;

    float v[PL];
    if (PL == 4) {
        float4 t = *(const float4*)(feat + (size_t)node * D + lane * 4);
        v[0] = t.x; v[1] = t.y; v[2] = t.z; v[3] = t.w;
    } else {
        float2 t = *(const float2*)(feat + (size_t)node * D + lane * 2);
        v[0] = t.x; v[1] = t.y;
    }
    float acc[8];
#pragma unroll
    for (int q = 0; q < 8; q++) {
        float s = 0.f;
#pragma unroll
        for (int j = 0; j < PL; j++)
            s = fmaf(v[j], sf[(lane * PL + j) * 8 + q], s);
        acc[q] = s;
    }
#pragma unroll
    for (int off = 16; off > 0; off >>= 1)
#pragma unroll
        for (int q = 0; q < 8; q++)
            acc[q] += __shfl_xor_sync(0xffffffffu, acc[q], off);
    if (lane == 0) {
        *(float4*)(als + (size_t)node * 4) = make_float4(acc[0], acc[1], acc[2], acc[3]);
        *(float4*)(ald + (size_t)node * 4) = make_float4(acc[4], acc[5], acc[6], acc[7]);
    }
}

// ---------------- CSR build ------------------------------------------------
__global__ void hist_kernel(const int* __restrict__ de, int E, int* __restrict__ cnt)
{
    int e = blockIdx.x * blockDim.x + threadIdx.x;
    if (e < E) atomicAdd(&cnt[de[e]], 1);
}

__global__ void scan_k1(int* __restrict__ data, int n, int* __restrict__ bsum)
{
    __shared__ int sh[256];
    int base = blockIdx.x * 2048 + threadIdx.x * 8;
    int v[8];
    int run = 0;
#pragma unroll
    for (int k = 0; k < 8; k++) {
        int t = (base + k < n) ? data[base + k] : 0;
        v[k] = run;
        run += t;
    }
    sh[threadIdx.x] = run;
    __syncthreads();
    for (int off = 1; off < 256; off <<= 1) {
        int t = (threadIdx.x >= off) ? sh[threadIdx.x - off] : 0;
        __syncthreads();
        sh[threadIdx.x] += t;
        __syncthreads();
    }
    int excl = sh[threadIdx.x] - run;
#pragma unroll
    for (int k = 0; k < 8; k++)
        if (base + k < n) data[base + k] = v[k] + excl;
    if (threadIdx.x == 255) bsum[blockIdx.x] = sh[255];
}

__global__ void scan_k2(int* __restrict__ bsum, int nb)
{
    if (threadIdx.x == 0) {
        int run = 0;
        for (int i = 0; i < nb; i++) { int t = bsum[i]; bsum[i] = run; run += t; }
    }
}

__global__ void scan_k3(int* __restrict__ data, int n, const int* __restrict__ bsum,
                        int* __restrict__ cursor, int E)
{
    int i = blockIdx.x * blockDim.x + threadIdx.x;
    if (i < n) {
        int v = data[i] + bsum[i >> 11];
        data[i] = v;
        cursor[i] = v;
    }
    if (i == 0) data[n] = E;
}

__global__ void scatter_kernel(const int* __restrict__ se, const int* __restrict__ de,
                               int E, int* __restrict__ cursor, int* __restrict__ ssrc)
{
    int e = blockIdx.x * blockDim.x + threadIdx.x;
    if (e < E) {
        int pos = atomicAdd(&cursor[de[e]], 1);
        ssrc[pos] = se[e];
    }
}

// ---------------- fused softmax-aggregate, CSR (layer 1) -------------------
// half-warp (16 lanes) per dst node, 2-edge unrolled, adds bias.
__global__ void agg1_kernel(const int* __restrict__ rowptr,
                            const int* __restrict__ ssrc,
                            const float* __restrict__ als,
                            const float* __restrict__ ald,
                            const float* __restrict__ h,
                            const float* __restrict__ bias,
                            float* __restrict__ out, int n)
{
    int gt   = blockIdx.x * blockDim.x + threadIdx.x;
    int node = gt >> 4;
    int li   = gt & 15;
    if (node >= n) return;
    int head = li >> 2;

    float aldv = ald[(size_t)node * 4 + head];

    float e0 = als[(size_t)node * 4 + head] + aldv;
    e0 = e0 > 0.f ? e0 : 0.2f * e0;
    float ex = __expf(e0);
    float den = ex;
    float4 hv = ((const float4*)(h + (size_t)node * 64))[li];
    float4 acc = make_float4(ex * hv.x, ex * hv.y, ex * hv.z, ex * hv.w);

    int j0 = rowptr[node], j1 = rowptr[node + 1];
    int j = j0;
    for (; j + 1 < j1; j += 2) {
        int s0 = ssrc[j], s1 = ssrc[j + 1];
        float ea = als[(size_t)s0 * 4 + head] + aldv;
        float eb = als[(size_t)s1 * 4 + head] + aldv;
        float4 v0 = ((const float4*)(h + (size_t)s0 * 64))[li];
        float4 v1 = ((const float4*)(h + (size_t)s1 * 64))[li];
        ea = ea > 0.f ? ea : 0.2f * ea;
        eb = eb > 0.f ? eb : 0.2f * eb;
        float w0 = __expf(ea);
        float w1 = __expf(eb);
        den += w0 + w1;
        acc.x = fmaf(w0, v0.x, acc.x); acc.x = fmaf(w1, v1.x, acc.x);
        acc.y = fmaf(w0, v0.y, acc.y); acc.y = fmaf(w1, v1.y, acc.y);
        acc.z = fmaf(w0, v0.z, acc.z); acc.z = fmaf(w1, v1.z, acc.z);
        acc.w = fmaf(w0, v0.w, acc.w); acc.w = fmaf(w1, v1.w, acc.w);
    }
    if (j < j1) {
        int s = ssrc[j];
        float e = als[(size_t)s * 4 + head] + aldv;
        e = e > 0.f ? e : 0.2f * e;
        float w = __expf(e);
        den += w;
        float4 v = ((const float4*)(h + (size_t)s * 64))[li];
        acc.x = fmaf(w, v.x, acc.x);
        acc.y = fmaf(w, v.y, acc.y);
        acc.z = fmaf(w, v.z, acc.z);
        acc.w = fmaf(w, v.w, acc.w);
    }
    float inv = 1.f / den;
    float4 o;
    o.x = acc.x * inv + bias[li * 4 + 0];
    o.y = acc.y * inv + bias[li * 4 + 1];
    o.z = acc.z * inv + bias[li * 4 + 2];
    o.w = acc.w * inv + bias[li * 4 + 3];
    ((float4*)(out + (size_t)node * 64))[li] = o;
}

// ---------------- layer 2: aggregate + head-mean + bias + elu + logsoftmax -
// warp per node, 2-edge unrolled, fully fused epilogue.
__global__ void agg2_final_kernel(const int* __restrict__ rowptr,
                                  const int* __restrict__ ssrc,
                                  const float* __restrict__ als,
                                  const float* __restrict__ ald,
                                  const float* __restrict__ h,
                                  const float* __restrict__ b2,
                                  float* __restrict__ y, int n)
{
    int lane = threadIdx.x & 31;
    int node = (blockIdx.x * blockDim.x + threadIdx.x) >> 5;
    if (node >= n) return;
    int head = lane >> 3;

    float aldv = ald[(size_t)node * 4 + head];

    float e0 = als[(size_t)node * 4 + head] + aldv;
    e0 = e0 > 0.f ? e0 : 0.2f * e0;
    float ex = __expf(e0);
    float den = ex;
    float4 hv = ((const float4*)(h + (size_t)node * 128))[lane];
    float4 acc = make_float4(ex * hv.x, ex * hv.y, ex * hv.z, ex * hv.w);

    int j0 = rowptr[node], j1 = rowptr[node + 1];
    int j = j0;
    for (; j + 1 < j1; j += 2) {
        int s0 = ssrc[j], s1 = ssrc[j + 1];
        float ea = als[(size_t)s0 * 4 + head] + aldv;
        float eb = als[(size_t)s1 * 4 + head] + aldv;
        float4 v0 = ((const float4*)(h + (size_t)s0 * 128))[lane];
        float4 v1 = ((const float4*)(h + (size_t)s1 * 128))[lane];
        ea = ea > 0.f ? ea : 0.2f * ea;
        eb = eb > 0.f ? eb : 0.2f * eb;
        float w0 = __expf(ea);
        float w1 = __expf(eb);
        den += w0 + w1;
        acc.x = fmaf(w0, v0.x, acc.x); acc.x = fmaf(w1, v1.x, acc.x);
        acc.y = fmaf(w0, v0.y, acc.y); acc.y = fmaf(w1, v1.y, acc.y);
        acc.z = fmaf(w0, v0.z, acc.z); acc.z = fmaf(w1, v1.z, acc.z);
        acc.w = fmaf(w0, v0.w, acc.w); acc.w = fmaf(w1, v1.w, acc.w);
    }
    if (j < j1) {
        int s = ssrc[j];
        float e = als[(size_t)s * 4 + head] + aldv;
        e = e > 0.f ? e : 0.2f * e;
        float w = __expf(e);
        den += w;
        float4 v = ((const float4*)(h + (size_t)s * 128))[lane];
        acc.x = fmaf(w, v.x, acc.x);
        acc.y = fmaf(w, v.y, acc.y);
        acc.z = fmaf(w, v.z, acc.z);
        acc.w = fmaf(w, v.w, acc.w);
    }
    float inv = 1.f / den;
    float4 v = make_float4(acc.x * inv, acc.y * inv, acc.z * inv, acc.w * inv);

    v.x += __shfl_xor_sync(0xffffffffu, v.x, 8);
    v.y += __shfl_xor_sync(0xffffffffu, v.y, 8);
    v.z += __shfl_xor_sync(0xffffffffu, v.z, 8);
    v.w += __shfl_xor_sync(0xffffffffu, v.w, 8);
    v.x += __shfl_xor_sync(0xffffffffu, v.x, 16);
    v.y += __shfl_xor_sync(0xffffffffu, v.y, 16);
    v.z += __shfl_xor_sync(0xffffffffu, v.z, 16);
    v.w += __shfl_xor_sync(0xffffffffu, v.w, 16);
    int c0 = (lane & 7) * 4;
    v.x = 0.25f * v.x + b2[c0 + 0];
    v.y = 0.25f * v.y + b2[c0 + 1];
    v.z = 0.25f * v.z + b2[c0 + 2];
    v.w = 0.25f * v.w + b2[c0 + 3];
    v.x = v.x > 0.f ? v.x : expm1f(v.x);
    v.y = v.y > 0.f ? v.y : expm1f(v.y);
    v.z = v.z > 0.f ? v.z : expm1f(v.z);
    v.w = v.w > 0.f ? v.w : expm1f(v.w);
    float m = fmaxf(fmaxf(v.x, v.y), fmaxf(v.z, v.w));
#pragma unroll
    for (int off = 1; off < 8; off <<= 1)
        m = fmaxf(m, __shfl_xor_sync(0xffffffffu, m, off));
    float s = expf(v.x - m) + expf(v.y - m) + expf(v.z - m) + expf(v.w - m);
#pragma unroll
    for (int off = 1; off < 8; off <<= 1)
        s += __shfl_xor_sync(0xffffffffu, s, off);
    float ls = m + logf(s);
    if (lane < 8) {
        float4 o = make_float4(v.x - ls, v.y - ls, v.z - ls, v.w - ls);
        ((float4*)(y + (size_t)node * 32))[lane] = o;
    }
}

// ---------------------------------------------------------------------------
extern "C" void kernel_launch(void* const* d_in, const int* in_sizes, int n_in,
                              void* d_out, int out_size)
{
    const float* x   = (const float*)d_in[0];
    const int*   ei  = (const int*)d_in[1];
    const float* W1  = (const float*)d_in[2];
    const float* as1 = (const float*)d_in[3];
    const float* ad1 = (const float*)d_in[4];
    const float* b1  = (const float*)d_in[5];
    const float* W2  = (const float*)d_in[6];
    const float* as2 = (const float*)d_in[7];
    const float* ad2 = (const float*)d_in[8];
    const float* b2  = (const float*)d_in[9];
    float*       y   = (float*)d_out;

    const int n = in_sizes[0] / 128;
    const int E = in_sizes[1] / 2;
    const int* se = ei;
    const int* de = ei + E;

    float *h1, *als1, *ald1, *out1, *h2, *als2, *ald2, *fold1, *fold2;
    int *rowptr, *cursor, *bsum, *ssrc;
    cudaGetSymbolAddress((void**)&h1,     g_h1);
    cudaGetSymbolAddress((void**)&als1,   g_als1);
    cudaGetSymbolAddress((void**)&ald1,   g_ald1);
    cudaGetSymbolAddress((void**)&out1,   g_out1);
    cudaGetSymbolAddress((void**)&h2,     g_h2);
    cudaGetSymbolAddress((void**)&als2,   g_als2);
    cudaGetSymbolAddress((void**)&ald2,   g_ald2);
    cudaGetSymbolAddress((void**)&fold1,  g_fold1);
    cudaGetSymbolAddress((void**)&fold2,  g_fold2);
    cudaGetSymbolAddress((void**)&rowptr, g_rowptr);
    cudaGetSymbolAddress((void**)&cursor, g_cursor);
    cudaGetSymbolAddress((void**)&bsum,   g_bsum);
    cudaGetSymbolAddress((void**)&ssrc,   g_ssrc);

    static cudaStream_t s2 = nullptr;
    static cudaEvent_t evFork = nullptr, evJoin = nullptr;
    static cudaEvent_t evFork2 = nullptr, evJoin2 = nullptr;
    if (!s2) {
        cudaStreamCreateWithFlags(&s2, cudaStreamNonBlocking);
        cudaEventCreateWithFlags(&evFork,  cudaEventDisableTiming);
        cudaEventCreateWithFlags(&evJoin,  cudaEventDisableTiming);
        cudaEventCreateWithFlags(&evFork2, cudaEventDisableTiming);
        cudaEventCreateWithFlags(&evJoin2, cudaEventDisableTiming);
    }

    const int nb = (n + 2047) / 2048;

    // ---- fork: folds + layer-1 logits + CSR build on s2 (hidden by gemm1) -
    cudaEventRecord(evFork, 0);
    cudaStreamWaitEvent(s2, evFork, 0);
    build_fold1<<<1, 1024, 0, s2>>>(W1, as1, ad1, fold1);
    build_fold2<<<1, 512, 0, s2>>>(W2, as2, ad2, fold2);
    al_fold_kernel<128><<<(int)(((long long)n * 32 + 255) / 256), 256, 0, s2>>>(
        x, fold1, als1, ald1, n);
    cudaMemsetAsync(rowptr, 0, (size_t)n * sizeof(int), s2);
    hist_kernel<<<(E + 255) / 256, 256, 0, s2>>>(de, E, rowptr);
    scan_k1<<<nb, 256, 0, s2>>>(rowptr, n, bsum);
    scan_k2<<<1, 32, 0, s2>>>(bsum, nb);
    scan_k3<<<(n + 255) / 256, 256, 0, s2>>>(rowptr, n, bsum, cursor, E);
    scatter_kernel<<<(E + 255) / 256, 256, 0, s2>>>(se, de, E, cursor, ssrc);
    cudaEventRecord(evJoin, s2);

    // ---- layer 1 dense part (main stream) ----
    gemm_kernel<128, 64><<<(n + 127) / 128, 128>>>(x, W1, h1, n);

    // ---- join, then layer-1 aggregation (adds b1) ----
    cudaStreamWaitEvent(0, evJoin, 0);
    agg1_kernel<<<(int)(((long long)n * 16 + 255) / 256), 256>>>(
        rowptr, ssrc, als1, ald1, h1, b1, out1, n);

    // ---- layer 2: logits on s2 (from out1), gemm2 on main, concurrent ----
    cudaEventRecord(evFork2, 0);
    cudaStreamWaitEvent(s2, evFork2, 0);
    al_fold_kernel<64><<<(int)(((long long)n * 32 + 255) / 256), 256, 0, s2>>>(
        out1, fold2, als2, ald2, n);
    cudaEventRecord(evJoin2, s2);

    gemm_kernel<64, 128><<<(n + 127) / 128, 256>>>(out1, W2, h2, n);

    cudaStreamWaitEvent(0, evJoin2, 0);
    agg2_final_kernel<<<(int)(((long long)n * 32 + 255) / 256), 256>>>(
        rowptr, ssrc, als2, ald2, h2, b2, y, n);
}

// round 8
// speedup vs baseline: 1.3794x; 1.3794x over previous
#include <cuda_runtime.h>
#include <cstdint>

#define MAX_N 100000
#define MAX_E 1600000

// ---------------- scratch (static __device__ arrays) ----------------------
__device__ float g_h1  [MAX_N * 64];
__device__ float g_als1[MAX_N * 4];
__device__ float g_ald1[MAX_N * 4];
__device__ float g_out1[MAX_N * 64];
__device__ float g_h2  [MAX_N * 128];
__device__ float g_als2[MAX_N * 4];
__device__ float g_ald2[MAX_N * 4];
__device__ int   g_rowptr[MAX_N + 1];
__device__ int   g_cursor[MAX_N];
__device__ int   g_bsum[128];
__device__ int   g_ssrc[MAX_E];

// ---------------- packed f32x2 helpers (sm_100+, non-'a' feature) ---------
__device__ __forceinline__ void fma2(unsigned long long& d,
                                     unsigned long long a,
                                     unsigned long long b) {
    asm("fma.rn.f32x2 %0, %1, %2, %3;" : "=l"(d) : "l"(a), "l"(b), "l"(d));
}
__device__ __forceinline__ unsigned long long splat2(float x) {
    unsigned long long r;
    asm("mov.b64 %0, {%1, %1};" : "=l"(r) : "f"(x));
    return r;
}

// ---------------- GEMM: C[M,NC] = A[M,K] @ W[K,NC], packed f32x2 ----------
// tile 128 x NC, micro 8x8 per thread, A-tile stored transposed so each
// thread's 8 row-values load as 2x ulonglong2 (= ready-made f32x2 pairs).
template<int K, int NC>
__global__ __launch_bounds__(16 * (NC / 8))
void gemm_kernel(const float* __restrict__ A, const float* __restrict__ W,
                 float* __restrict__ C, int M)
{
    constexpr int KC = 32;
    constexpr int TX = NC / 8;               // 8 (NC=64) or 16 (NC=128)
    constexpr int T  = 16 * TX;              // 128 or 256 threads
    constexpr int A_F4 = (128 * KC / 4) / T; // 8 or 4
    constexpr int B_F4 = (KC * NC / 4) / T;  // 4

    __shared__ __align__(16) float As[KC][132];   // transposed: As[k][row]
    __shared__ float Bs[KC][NC];

    const int tid = threadIdx.x;
    const int tx = tid % TX;
    const int ty = tid / TX;
    const int row0 = blockIdx.x * 128;

    float4 aPre[A_F4], bPre[B_F4];

    auto loadA = [&](int kk) {
#pragma unroll
        for (int t = 0; t < A_F4; t++) {
            int q = tid + t * T;
            int r = q >> 3, kc4 = q & 7;
            int gr = row0 + r;
            aPre[t] = (gr < M)
                ? *(const float4*)(A + (size_t)gr * K + kk + kc4 * 4)
                : make_float4(0.f, 0.f, 0.f, 0.f);
        }
    };
    auto loadB = [&](int kk) {
#pragma unroll
        for (int t = 0; t < B_F4; t++) {
            int q = tid + t * T;
            int r = q / (NC / 4), c4 = q % (NC / 4);
            bPre[t] = *(const float4*)(W + (size_t)(kk + r) * NC + c4 * 4);
        }
    };
    auto storeA = [&]() {             // transposed scatter
#pragma unroll
        for (int t = 0; t < A_F4; t++) {
            int q = tid + t * T;
            int r = q >> 3, kc4 = q & 7;
            As[kc4 * 4 + 0][r] = aPre[t].x;
            As[kc4 * 4 + 1][r] = aPre[t].y;
            As[kc4 * 4 + 2][r] = aPre[t].z;
            As[kc4 * 4 + 3][r] = aPre[t].w;
        }
    };
    auto storeB = [&]() {
#pragma unroll
        for (int t = 0; t < B_F4; t++) {
            int q = tid + t * T;
            int r = q / (NC / 4), c4 = q % (NC / 4);
            *(float4*)&Bs[r][c4 * 4] = bPre[t];
        }
    };

    unsigned long long acc2[4][8];    // [row-pair][col], each = 2 fp32
#pragma unroll
    for (int i = 0; i < 4; i++)
#pragma unroll
        for (int j = 0; j < 8; j++) acc2[i][j] = 0ull;

    loadA(0); loadB(0);
    storeA(); storeB();
    __syncthreads();

    for (int kk = KC; kk <= K; kk += KC) {
        const bool more = (kk < K);
        if (more) { loadA(kk); loadB(kk); }

#pragma unroll
        for (int k = 0; k < KC; k++) {
            // a: 8 row-values = 2x ulonglong2 = 4 packed pairs, zero pack cost
            ulonglong2 ap0 = *(const ulonglong2*)&As[k][ty * 8];
            ulonglong2 ap1 = *(const ulonglong2*)&As[k][ty * 8 + 4];
            unsigned long long ap[4] = {ap0.x, ap0.y, ap1.x, ap1.y};
            float4 b0 = *(float4*)&Bs[k][tx * 8];
            float4 b1 = *(float4*)&Bs[k][tx * 8 + 4];
            unsigned long long bs[8] = {
                splat2(b0.x), splat2(b0.y), splat2(b0.z), splat2(b0.w),
                splat2(b1.x), splat2(b1.y), splat2(b1.z), splat2(b1.w)
            };
#pragma unroll
            for (int i = 0; i < 4; i++)
#pragma unroll
                for (int j = 0; j < 8; j++)
                    fma2(acc2[i][j], ap[i], bs[j]);
        }
        __syncthreads();
        if (more) {
            storeA(); storeB();
            __syncthreads();
        }
    }

    // unpack + store: acc2[i][j] holds rows (ty*8+2i, ty*8+2i+1), col tx*8+j
#pragma unroll
    for (int i = 0; i < 4; i++) {
        float2 p[8];
#pragma unroll
        for (int j = 0; j < 8; j++) p[j] = *(float2*)&acc2[i][j];
#pragma unroll
        for (int half = 0; half < 2; half++) {
            int gr = row0 + ty * 8 + 2 * i + half;
            if (gr < M) {
                float* cp = C + (size_t)gr * NC + tx * 8;
                float v0 = half ? p[0].y : p[0].x;
                float v1 = half ? p[1].y : p[1].x;
                float v2 = half ? p[2].y : p[2].x;
                float v3 = half ? p[3].y : p[3].x;
                float v4 = half ? p[4].y : p[4].x;
                float v5 = half ? p[5].y : p[5].x;
                float v6 = half ? p[6].y : p[6].x;
                float v7 = half ? p[7].y : p[7].x;
                *(float4*)(cp)     = make_float4(v0, v1, v2, v3);
                *(float4*)(cp + 4) = make_float4(v4, v5, v6, v7);
            }
        }
    }
}

// ---------------- attention logits ----------------------------------------
template<int C>
__global__ void al_kernel(const float* __restrict__ h,
                          const float* __restrict__ a_src,
                          const float* __restrict__ a_dst,
                          float* __restrict__ als, float* __restrict__ ald, int n)
{
    int t = blockIdx.x * blockDim.x + threadIdx.x;
    if (t >= n * 4) return;
    int node = t >> 2, head = t & 3;
    const float* hp  = h + (size_t)node * (4 * C) + head * C;
    const float* asp = a_src + head * C;
    const float* adp = a_dst + head * C;
    float s1 = 0.f, s2 = 0.f;
#pragma unroll
    for (int c = 0; c < C; c += 4) {
        float4 hv = *(const float4*)(hp + c);
        float4 av = *(const float4*)(asp + c);
        float4 dv = *(const float4*)(adp + c);
        s1 += hv.x * av.x + hv.y * av.y + hv.z * av.z + hv.w * av.w;
        s2 += hv.x * dv.x + hv.y * dv.y + hv.z * dv.z + hv.w * dv.w;
    }
    als[t] = s1;
    ald[t] = s2;
}

// ---------------- CSR build ------------------------------------------------
__global__ void hist_kernel(const int* __restrict__ de, int E, int* __restrict__ cnt)
{
    int e = blockIdx.x * blockDim.x + threadIdx.x;
    if (e < E) atomicAdd(&cnt[de[e]], 1);
}

__global__ void scan_k1(int* __restrict__ data, int n, int* __restrict__ bsum)
{
    __shared__ int sh[256];
    int base = blockIdx.x * 2048 + threadIdx.x * 8;
    int v[8];
    int run = 0;
#pragma unroll
    for (int k = 0; k < 8; k++) {
        int t = (base + k < n) ? data[base + k] : 0;
        v[k] = run;
        run += t;
    }
    sh[threadIdx.x] = run;
    __syncthreads();
    for (int off = 1; off < 256; off <<= 1) {
        int t = (threadIdx.x >= off) ? sh[threadIdx.x - off] : 0;
        __syncthreads();
        sh[threadIdx.x] += t;
        __syncthreads();
    }
    int excl = sh[threadIdx.x] - run;
#pragma unroll
    for (int k = 0; k < 8; k++)
        if (base + k < n) data[base + k] = v[k] + excl;
    if (threadIdx.x == 255) bsum[blockIdx.x] = sh[255];
}

__global__ void scan_k2(int* __restrict__ bsum, int nb)
{
    if (threadIdx.x == 0) {
        int run = 0;
        for (int i = 0; i < nb; i++) { int t = bsum[i]; bsum[i] = run; run += t; }
    }
}

__global__ void scan_k3(int* __restrict__ data, int n, const int* __restrict__ bsum,
                        int* __restrict__ cursor, int E)
{
    int i = blockIdx.x * blockDim.x + threadIdx.x;
    if (i < n) {
        int v = data[i] + bsum[i >> 11];
        data[i] = v;
        cursor[i] = v;
    }
    if (i == 0) data[n] = E;
}

__global__ void scatter_kernel(const int* __restrict__ se, const int* __restrict__ de,
                               int E, int* __restrict__ cursor, int* __restrict__ ssrc)
{
    int e = blockIdx.x * blockDim.x + threadIdx.x;
    if (e < E) {
        int pos = atomicAdd(&cursor[de[e]], 1);
        ssrc[pos] = se[e];
    }
}

// ---------------- fused softmax-aggregate, CSR (layer 1) -------------------
template<int C>
__global__ void agg_csr_kernel(const int* __restrict__ rowptr,
                               const int* __restrict__ ssrc,
                               const float* __restrict__ als,
                               const float* __restrict__ ald,
                               const float* __restrict__ h,
                               const float* __restrict__ bias,
                               float* __restrict__ out, int n)
{
    constexpr int HC = 4 * C;
    constexpr int G  = HC / 4;
    int gt   = blockIdx.x * blockDim.x + threadIdx.x;
    int node = gt / G;
    int li   = gt % G;
    if (node >= n) return;
    int head = li / (C / 4);

    float aldv = ald[(size_t)node * 4 + head];

    float e0 = als[(size_t)node * 4 + head] + aldv;
    e0 = e0 > 0.f ? e0 : 0.2f * e0;
    float ex = __expf(e0);
    float den = ex;
    float4 hv = ((const float4*)(h + (size_t)node * HC))[li];
    float4 acc = make_float4(ex * hv.x, ex * hv.y, ex * hv.z, ex * hv.w);

    int j1 = rowptr[node + 1];
    for (int j = rowptr[node]; j < j1; j++) {
        int s = ssrc[j];
        float e = als[(size_t)s * 4 + head] + aldv;
        e = e > 0.f ? e : 0.2f * e;
        float w = __expf(e);
        den += w;
        float4 v = ((const float4*)(h + (size_t)s * HC))[li];
        acc.x = fmaf(w, v.x, acc.x);
        acc.y = fmaf(w, v.y, acc.y);
        acc.z = fmaf(w, v.z, acc.z);
        acc.w = fmaf(w, v.w, acc.w);
    }
    float inv = 1.f / den;
    float4 o;
    o.x = acc.x * inv + bias[li * 4 + 0];
    o.y = acc.y * inv + bias[li * 4 + 1];
    o.z = acc.z * inv + bias[li * 4 + 2];
    o.w = acc.w * inv + bias[li * 4 + 3];
    ((float4*)(out + (size_t)node * HC))[li] = o;
}

// ---------------- layer 2: aggregate + head-mean + bias + elu + logsoftmax -
__global__ void agg2_final_kernel(const int* __restrict__ rowptr,
                                  const int* __restrict__ ssrc,
                                  const float* __restrict__ als,
                                  const float* __restrict__ ald,
                                  const float* __restrict__ h,
                                  const float* __restrict__ b2,
                                  float* __restrict__ y, int n)
{
    int lane = threadIdx.x & 31;
    int node = (blockIdx.x * blockDim.x + threadIdx.x) >> 5;
    if (node >= n) return;
    int head = lane >> 3;

    float aldv = ald[(size_t)node * 4 + head];

    float e0 = als[(size_t)node * 4 + head] + aldv;
    e0 = e0 > 0.f ? e0 : 0.2f * e0;
    float ex = __expf(e0);
    float den = ex;
    float4 hv = ((const float4*)(h + (size_t)node * 128))[lane];
    float4 acc = make_float4(ex * hv.x, ex * hv.y, ex * hv.z, ex * hv.w);

    int j1 = rowptr[node + 1];
    for (int j = rowptr[node]; j < j1; j++) {
        int s = ssrc[j];
        float e = als[(size_t)s * 4 + head] + aldv;
        e = e > 0.f ? e : 0.2f * e;
        float w = __expf(e);
        den += w;
        float4 v = ((const float4*)(h + (size_t)s * 128))[lane];
        acc.x = fmaf(w, v.x, acc.x);
        acc.y = fmaf(w, v.y, acc.y);
        acc.z = fmaf(w, v.z, acc.z);
        acc.w = fmaf(w, v.w, acc.w);
    }
    float inv = 1.f / den;
    float4 v = make_float4(acc.x * inv, acc.y * inv, acc.z * inv, acc.w * inv);

    v.x += __shfl_xor_sync(0xffffffffu, v.x, 8);
    v.y += __shfl_xor_sync(0xffffffffu, v.y, 8);
    v.z += __shfl_xor_sync(0xffffffffu, v.z, 8);
    v.w += __shfl_xor_sync(0xffffffffu, v.w, 8);
    v.x += __shfl_xor_sync(0xffffffffu, v.x, 16);
    v.y += __shfl_xor_sync(0xffffffffu, v.y, 16);
    v.z += __shfl_xor_sync(0xffffffffu, v.z, 16);
    v.w += __shfl_xor_sync(0xffffffffu, v.w, 16);
    int c0 = (lane & 7) * 4;
    v.x = 0.25f * v.x + b2[c0 + 0];
    v.y = 0.25f * v.y + b2[c0 + 1];
    v.z = 0.25f * v.z + b2[c0 + 2];
    v.w = 0.25f * v.w + b2[c0 + 3];
    v.x = v.x > 0.f ? v.x : expm1f(v.x);
    v.y = v.y > 0.f ? v.y : expm1f(v.y);
    v.z = v.z > 0.f ? v.z : expm1f(v.z);
    v.w = v.w > 0.f ? v.w : expm1f(v.w);
    float m = fmaxf(fmaxf(v.x, v.y), fmaxf(v.z, v.w));
#pragma unroll
    for (int off = 1; off < 8; off <<= 1)
        m = fmaxf(m, __shfl_xor_sync(0xffffffffu, m, off));
    float s = expf(v.x - m) + expf(v.y - m) + expf(v.z - m) + expf(v.w - m);
#pragma unroll
    for (int off = 1; off < 8; off <<= 1)
        s += __shfl_xor_sync(0xffffffffu, s, off);
    float ls = m + logf(s);
    if (lane < 8) {
        float4 o = make_float4(v.x - ls, v.y - ls, v.z - ls, v.w - ls);
        ((float4*)(y + (size_t)node * 32))[lane] = o;
    }
}

// ---------------------------------------------------------------------------
extern "C" void kernel_launch(void* const* d_in, const int* in_sizes, int n_in,
                              void* d_out, int out_size)
{
    const float* x   = (const float*)d_in[0];
    const int*   ei  = (const int*)d_in[1];
    const float* W1  = (const float*)d_in[2];
    const float* as1 = (const float*)d_in[3];
    const float* ad1 = (const float*)d_in[4];
    const float* b1  = (const float*)d_in[5];
    const float* W2  = (const float*)d_in[6];
    const float* as2 = (const float*)d_in[7];
    const float* ad2 = (const float*)d_in[8];
    const float* b2  = (const float*)d_in[9];
    float*       y   = (float*)d_out;

    const int n = in_sizes[0] / 128;
    const int E = in_sizes[1] / 2;
    const int* se = ei;
    const int* de = ei + E;

    float *h1, *als1, *ald1, *out1, *h2, *als2, *ald2;
    int *rowptr, *cursor, *bsum, *ssrc;
    cudaGetSymbolAddress((void**)&h1,     g_h1);
    cudaGetSymbolAddress((void**)&als1,   g_als1);
    cudaGetSymbolAddress((void**)&ald1,   g_ald1);
    cudaGetSymbolAddress((void**)&out1,   g_out1);
    cudaGetSymbolAddress((void**)&h2,     g_h2);
    cudaGetSymbolAddress((void**)&als2,   g_als2);
    cudaGetSymbolAddress((void**)&ald2,   g_ald2);
    cudaGetSymbolAddress((void**)&rowptr, g_rowptr);
    cudaGetSymbolAddress((void**)&cursor, g_cursor);
    cudaGetSymbolAddress((void**)&bsum,   g_bsum);
    cudaGetSymbolAddress((void**)&ssrc,   g_ssrc);

    const int nb = (n + 2047) / 2048;

    // ---- CSR build (shared by both layers) ----
    cudaMemsetAsync(rowptr, 0, (size_t)n * sizeof(int));
    hist_kernel<<<(E + 255) / 256, 256>>>(de, E, rowptr);
    scan_k1<<<nb, 256>>>(rowptr, n, bsum);
    scan_k2<<<1, 32>>>(bsum, nb);
    scan_k3<<<(n + 255) / 256, 256>>>(rowptr, n, bsum, cursor, E);
    scatter_kernel<<<(E + 255) / 256, 256>>>(se, de, E, cursor, ssrc);

    // ---- layer 1 ----
    gemm_kernel<128, 64><<<(n + 127) / 128, 128>>>(x, W1, h1, n);
    al_kernel<16><<<(n * 4 + 255) / 256, 256>>>(h1, as1, ad1, als1, ald1, n);
    agg_csr_kernel<16><<<(int)(((long long)n * 16 + 255) / 256), 256>>>(
        rowptr, ssrc, als1, ald1, h1, b1, out1, n);

    // ---- layer 2 ----
    gemm_kernel<64, 128><<<(n + 127) / 128, 256>>>(out1, W2, h2, n);
    al_kernel<32><<<(n * 4 + 255) / 256, 256>>>(h2, as2, ad2, als2, ald2, n);
    agg2_final_kernel<<<(int)(((long long)n * 32 + 255) / 256), 256>>>(
        rowptr, ssrc, als2, ald2, h2, b2, y, n);
}